// round 15
// baseline (speedup 1.0000x reference)
#include <cuda_runtime.h>
#include <cstdint>

// DisulfideEnergy: sulfur-pair energy scatter + fused residue reduction.
//
// Output (single f32 buffer):
//   [0 .. 64000)              resi_energy (8,4,500,4)
//   [64000 .. 2064000)        atom_energy (500000,4)
//   [2064000 .. 6064000)      sulfur      (4000000) as 0.0/1.0

#define N_CHAINS   4
#define N_RES      500
#define SG_CODE    7
#define MAX_ATOMS  500000
#define MAX_WORDS  ((MAX_ATOMS + 31) / 32)   // 15625
#define PBLOCK     1024

__device__ __align__(16) uint32_t g_sgmask[MAX_WORDS + 32];

// ---------------------------------------------------------------------------
// Kernel 1: build SG bitmask (4 atoms/thread, MLP=4) AND zero resi+atomE.
// ---------------------------------------------------------------------------
__global__ void mask_zero_kernel(const int* __restrict__ desc,
                                 float* __restrict__ out,
                                 int n_atoms, int zero_float4s)
{
    int base = blockIdx.x * 1024;
    int an[4];
#pragma unroll
    for (int u = 0; u < 4; u++) {
        int a = base + u * 256 + threadIdx.x;
        an[u] = (a < n_atoms) ? __ldcs(desc + 4 * a) : 0;   // at_name column
    }
#pragma unroll
    for (int u = 0; u < 4; u++) {
        int a = base + u * 256 + threadIdx.x;
        unsigned ball = __ballot_sync(0xffffffffu, an[u] == SG_CODE);
        if ((threadIdx.x & 31) == 0 && a < n_atoms)
            g_sgmask[a >> 5] = ball;
    }

    // zero resi + atom_energy regions (grid-stride, float4)
    float4 z = make_float4(0.f, 0.f, 0.f, 0.f);
    int stride = gridDim.x * blockDim.x;
    for (int t = blockIdx.x * blockDim.x + threadIdx.x;
         t < zero_float4s; t += stride)
        __stcs(reinterpret_cast<float4*>(out) + t, z);
}

// ---------------------------------------------------------------------------
// Heavy path: one true sulfur pair. Updates atomE AND resi.
// ---------------------------------------------------------------------------
__device__ __forceinline__ void heavy_pair(int i, int j,
                                           const float* __restrict__ coords,
                                           const int4* __restrict__ desc4,
                                           const uint32_t* __restrict__ amask,
                                           float* __restrict__ atomE,
                                           float* __restrict__ resi)
{
    float dx = __ldg(coords + 3 * i + 0) - __ldg(coords + 3 * j + 0) + 1e-6f;
    float dy = __ldg(coords + 3 * i + 1) - __ldg(coords + 3 * j + 1) + 1e-6f;
    float dz = __ldg(coords + 3 * i + 2) - __ldg(coords + 3 * j + 2) + 1e-6f;
    float dist = sqrtf(dx * dx + dy * dy + dz * dz);

    int4 di = __ldg(desc4 + i);   // (at_name, resnum, batch, chain)
    int4 dj = __ldg(desc4 + j);

    float rd  = fabsf((float)(di.y - dj.y));
    float rds = (rd > 0.f) ? rd : 1.0f;

    // -0.001*298.0 = -0.298
    float energy = -0.298f * (2.1f + 2.9823825f * logf(rds))
                 + 5.0f * fabsf(dist - 2.04f);
    float net = 0.5f * energy;

    int flat_i = (di.z * N_CHAINS + di.w) * N_RES + di.y;
    int flat_j = (dj.z * N_CHAINS + dj.w) * N_RES + dj.y;

    uint4 mi = *reinterpret_cast<const uint4*>(amask + 4 * (size_t)i);
    uint4 mj = *reinterpret_cast<const uint4*>(amask + 4 * (size_t)j);

#define ALT(A, MI, MJ)                                                       \
    if ((MI) && (MJ)) {                                                      \
        atomicAdd(atomE + 4 * (size_t)i + (A), net);                         \
        atomicAdd(atomE + 4 * (size_t)j + (A), net);                         \
        atomicAdd(resi  + 4 * (size_t)flat_i + (A), net);                    \
        atomicAdd(resi  + 4 * (size_t)flat_j + (A), net);                    \
    }
    ALT(0, mi.x, mj.x)
    ALT(1, mi.y, mj.y)
    ALT(2, mi.z, mj.z)
    ALT(3, mi.w, mj.w)
#undef ALT
}

// Cold handler for a chunk of 2 pairs: single branch target in the hot loop.
__device__ __noinline__ void heavy_chunk(int4 a, unsigned s0, unsigned s1,
                                         const float* __restrict__ coords,
                                         const int4* __restrict__ desc4,
                                         const uint32_t* __restrict__ amask,
                                         float* __restrict__ atomE,
                                         float* __restrict__ resi)
{
    if (s0) heavy_pair(a.x, a.y, coords, desc4, amask, atomE, resi);
    if (s1) heavy_pair(a.z, a.w, coords, desc4, amask, atomE, resi);
}

// ---------------------------------------------------------------------------
// Kernel 2: pair sweep — branchless hot loop, SEL-broadcast second lookup.
// Pairs loaded with NORMAL cache policy (__ldg): the 32MB array fits L2,
// so graph replays 2..N source pairs at L2 latency instead of DRAM.
// First prefetch issued BEFORE mask staging to overlap its latency.
// 1024 thr x 2 CTAs/SM = 64 warps/SM (32 regs), 2 pairs/iter.
// ---------------------------------------------------------------------------
__global__ void __launch_bounds__(PBLOCK, 2)
pair_kernel(const int4* __restrict__ pairs2,
            const float* __restrict__ coords,
            const int4* __restrict__ desc4,
            const uint32_t* __restrict__ amask,
            float* __restrict__ out,
            int n_pairs, int n_atoms, int resi_floats)
{
    extern __shared__ __align__(16) uint32_t smask[];
    int nwords = (n_atoms + 31) >> 5;

    int n2 = n_pairs >> 1;                     // int4 groups (2 pairs each)
    int stride = gridDim.x * blockDim.x;
    int idx = blockIdx.x * blockDim.x + threadIdx.x;

    // Issue the first pairs load BEFORE mask staging: its ~250-600 cyc
    // latency overlaps the mask copy + barrier.
    int4 a;
    bool valid = idx < n2;
    if (valid) a = __ldg(pairs2 + idx);

    // stage mask (vectorized)
    {
        int nw4 = nwords >> 2;
        const uint4* gm4 = reinterpret_cast<const uint4*>(g_sgmask);
        uint4* sm4 = reinterpret_cast<uint4*>(smask);
        for (int w = threadIdx.x; w < nw4; w += blockDim.x)
            sm4[w] = gm4[w];
        for (int w = (nw4 << 2) + threadIdx.x; w < nwords; w += blockDim.x)
            smask[w] = g_sgmask[w];
    }
    __syncthreads();

    float* resi  = out;
    float* atomE = out + resi_floats;
    float* sout  = atomE + 4 * (size_t)n_atoms;

    if (valid) {
        do {
            // clamped unconditional prefetch (IMNMX, no branch)
            int nidx = idx + stride;
            int pidx = min(nidx, n2 - 1);
            int4 b = __ldg(pairs2 + pidx);

            // lookup 1 (random); lookup 2 routed to word 0 when bit1==0
            // (broadcast for ~97.5% of lanes -> ~2 phases instead of ~4)
            unsigned bi0 = (smask[(unsigned)a.x >> 5] >> (a.x & 31)) & 1u;
            unsigned bi1 = (smask[(unsigned)a.z >> 5] >> (a.z & 31)) & 1u;

            unsigned w0 = bi0 ? ((unsigned)a.y >> 5) : 0u;   // SEL
            unsigned w1 = bi1 ? ((unsigned)a.w >> 5) : 0u;   // SEL
            unsigned s0 = bi0 & (smask[w0] >> (a.y & 31));
            unsigned s1 = bi1 & (smask[w1] >> (a.w & 31));
            s0 &= 1u;
            s1 &= 1u;

            float2 so;
            so.x = (float)s0;                  // I2F, branch-free
            so.y = (float)s1;
            __stcs(reinterpret_cast<float2*>(sout) + idx, so);

            // single rarely-taken branch (p ~ 1/800 per pair)
            if (s0 | s1)
                heavy_chunk(a, s0, s1, coords, desc4, amask, atomE, resi);

            a = b;
            idx = nidx;
        } while (idx < n2);
    }

    // tail: odd pair (zero here, kept general)
    if ((n_pairs & 1) && blockIdx.x == 0 && threadIdx.x == 0) {
        const int* pp = reinterpret_cast<const int*>(pairs2);
        int i = pp[2 * (n_pairs - 1)], j = pp[2 * (n_pairs - 1) + 1];
        unsigned s = (smask[i >> 5] >> (i & 31))
                   & (smask[j >> 5] >> (j & 31)) & 1u;
        sout[n_pairs - 1] = s ? 1.0f : 0.0f;
        if (s) heavy_pair(i, j, coords, desc4, amask, atomE, resi);
    }
}

// ---------------------------------------------------------------------------
extern "C" void kernel_launch(void* const* d_in, const int* in_sizes, int n_in,
                              void* d_out, int out_size)
{
    const float*    coords = (const float*)d_in[0];
    const int*      desc   = (const int*)d_in[1];
    const int*      pairs  = (const int*)d_in[2];
    const uint32_t* amask  = (const uint32_t*)d_in[3];
    float*          out    = (float*)d_out;

    int n_atoms = in_sizes[0] / 3;
    int n_pairs = in_sizes[2] / 2;
    int n_alt   = in_sizes[3] / n_atoms;                      // 4
    int resi_floats = out_size - n_atoms * n_alt - n_pairs;   // 64000

    int nwords = (n_atoms + 31) >> 5;
    size_t smem = (size_t)((nwords + 3) & ~3) * 4;            // 62512 B

    cudaFuncSetAttribute(pair_kernel,
                         cudaFuncAttributeMaxDynamicSharedMemorySize,
                         (int)smem);

    // Mask build + zero resi/atomE regions in one kernel.
    int mblocks = (n_atoms + 1023) / 1024;
    int zero_float4s = (resi_floats + n_atoms * n_alt) / 4;
    mask_zero_kernel<<<mblocks, 256>>>(desc, out, n_atoms, zero_float4s);

    // 2 CTAs/SM x 1024 threads = 64 warps/SM.
    pair_kernel<<<296, PBLOCK, smem>>>((const int4*)pairs, coords,
                                       (const int4*)desc, amask,
                                       out, n_pairs, n_atoms, resi_floats);
}